// round 1
// baseline (speedup 1.0000x reference)
#include <cuda_runtime.h>
#include <math.h>

#define BLK 128

// ---------------- packed weight layout (floats) ----------------
// All sections 16B-aligned, K padded to multiple of 4, pads are ZERO.
constexpr int OFF_HT  = 0;        // 30 x 40   (in = [x(8), hidden(30), 0, 0])
constexpr int OFF_BHT = 1200;     // 30 (pad 32)
constexpr int OFF_W0  = 1232;     // 30 x 32   (W0eff = W0[:, :30] + W0[:, 30:])
constexpr int OFF_B0  = 2192;     // 30 (pad 32)
constexpr int OFF_W1  = 2224;     // 45 x 32
constexpr int OFF_B1  = 3664;     // 45 (pad 48)
constexpr int OFF_W2  = 3712;     // 40 x 48
constexpr int OFF_B2  = 5632;     // 40
constexpr int OFF_W3  = 5672;     // 30 x 40
constexpr int OFF_B3  = 6872;     // 30 (pad 32)
constexpr int OFF_GW  = 6904;     // 30 x 4 x 32  (gate rows interleaved per j: i,f,o,g)
constexpr int OFF_BG  = 10744;    // 30 x 4
constexpr int OFF_PW  = 10864;    // 32  (folded p2@p1)
constexpr int OFF_PB  = 10896;    // 1
constexpr int WTOT    = 10912;    // padded total (mult of 4)

__device__ float g_w[WTOT];

// shared layout: [0, WTOT) weights, then act(48*BLK), cell(32*BLK), hid(32*BLK)
constexpr int SM_FLOATS = WTOT + 48 * BLK + 32 * BLK + 32 * BLK;
constexpr int SM_BYTES  = SM_FLOATS * 4;

// ---------------- prep kernel: fold + pack weights ----------------
__global__ void prep_kernel(
    const float* __restrict__ ht_W, const float* __restrict__ ht_b,
    const float* __restrict__ m_W0, const float* __restrict__ m_b0,
    const float* __restrict__ m_W1, const float* __restrict__ m_b1,
    const float* __restrict__ m_W2, const float* __restrict__ m_b2,
    const float* __restrict__ m_W3, const float* __restrict__ m_b3,
    const float* __restrict__ gW,   const float* __restrict__ gb,
    const float* __restrict__ p1W,  const float* __restrict__ p1b,
    const float* __restrict__ p2W,  const float* __restrict__ p2b)
{
    const int tid = threadIdx.x;
    const int NT  = blockDim.x;
    for (int i = tid; i < WTOT; i += NT) g_w[i] = 0.0f;
    __syncthreads();

    // ht_W (30 x 38) -> 30 x 40
    for (int i = tid; i < 30 * 38; i += NT)
        g_w[OFF_HT + (i / 38) * 40 + (i % 38)] = ht_W[i];
    for (int i = tid; i < 30; i += NT) g_w[OFF_BHT + i] = ht_b[i];

    // W0eff (30 x 30) -> 30 x 32
    for (int i = tid; i < 30 * 30; i += NT) {
        int j = i / 30, k = i % 30;
        g_w[OFF_W0 + j * 32 + k] = m_W0[j * 60 + k] + m_W0[j * 60 + 30 + k];
    }
    for (int i = tid; i < 30; i += NT) g_w[OFF_B0 + i] = m_b0[i];

    // W1 (45 x 30) -> 45 x 32
    for (int i = tid; i < 45 * 30; i += NT)
        g_w[OFF_W1 + (i / 30) * 32 + (i % 30)] = m_W1[i];
    for (int i = tid; i < 45; i += NT) g_w[OFF_B1 + i] = m_b1[i];

    // W2 (40 x 45) -> 40 x 48
    for (int i = tid; i < 40 * 45; i += NT)
        g_w[OFF_W2 + (i / 45) * 48 + (i % 45)] = m_W2[i];
    for (int i = tid; i < 40; i += NT) g_w[OFF_B2 + i] = m_b2[i];

    // W3 (30 x 40) -> 30 x 40 (no pad needed)
    for (int i = tid; i < 30 * 40; i += NT)
        g_w[OFF_W3 + i] = m_W3[i];
    for (int i = tid; i < 30; i += NT) g_w[OFF_B3 + i] = m_b3[i];

    // g_W (120 x 30): interleave the 4 gate rows for each j -> [j][g][32]
    for (int i = tid; i < 120 * 30; i += NT) {
        int r = i / 30, k = i % 30;
        int g = r / 30, jj = r % 30;
        g_w[OFF_GW + (jj * 4 + g) * 32 + k] = gW[i];
    }
    for (int i = tid; i < 120; i += NT) {
        int g = i / 30, jj = i % 30;
        g_w[OFF_BG + jj * 4 + g] = gb[i];
    }

    // fold predict heads: pw[k] = sum_i p2W[i] * p1W[i][k];  pb = p2b + sum_i p2W[i]*p1b[i]
    for (int k = tid; k < 30; k += NT) {
        float s = 0.0f;
        for (int i = 0; i < 10; ++i) s += p2W[i] * p1W[i * 30 + k];
        g_w[OFF_PW + k] = s;
    }
    if (tid == 0) {
        float s = p2b[0];
        for (int i = 0; i < 10; ++i) s += p2W[i] * p1b[i];
        g_w[OFF_PB] = s;
    }
}

// ---------------- math helpers (accurate: EX2 + RCP MUFU, ~1e-6 rel err) ----------------
__device__ __forceinline__ float tanh_fast(float x)
{
    float ax = fabsf(x);
    float e  = __expf(ax * -2.0f);
    float r  = __fdividef(1.0f - e, 1.0f + e);
    return copysignf(r, x);
}

__device__ __forceinline__ float sigmoid_fast(float x)
{
    return __fdividef(1.0f, 1.0f + __expf(-x));
}

// ---------------- dense layer: a(regs) @ W^T + b -> per-thread smem slots ----------------
template <int KP, int N, bool TANH>
__device__ __forceinline__ void dense(const float* __restrict__ w,
                                      const float* __restrict__ bias,
                                      const float (&a)[48],
                                      float* __restrict__ outbuf, int tid)
{
#pragma unroll 1
    for (int j = 0; j < N; ++j) {
        const float4* wr = reinterpret_cast<const float4*>(w + j * KP);
        float s0 = 0.f, s1 = 0.f, s2 = 0.f, s3 = 0.f;
#pragma unroll
        for (int q = 0; q < KP / 4; ++q) {
            float4 wv = wr[q];
            s0 = fmaf(wv.x, a[4 * q + 0], s0);
            s1 = fmaf(wv.y, a[4 * q + 1], s1);
            s2 = fmaf(wv.z, a[4 * q + 2], s2);
            s3 = fmaf(wv.w, a[4 * q + 3], s3);
        }
        float r = ((s0 + s1) + (s2 + s3)) + bias[j];
        if (TANH) r = tanh_fast(r);
        outbuf[j * BLK + tid] = r;
    }
}

template <int K, int KP>
__device__ __forceinline__ void load_act(float (&a)[48], const float* __restrict__ buf, int tid)
{
#pragma unroll
    for (int k = 0; k < KP; ++k) a[k] = (k < K) ? buf[k * BLK + tid] : 0.0f;
}

// ---------------- main persistent kernel ----------------
__global__ void __launch_bounds__(BLK, 2)
lstm_main(const float* __restrict__ x, float* __restrict__ out, int n)
{
    extern __shared__ float sm[];
    const int tid = threadIdx.x;

    // cooperative weight copy (vectorized)
    {
        const float4* src = reinterpret_cast<const float4*>(g_w);
        float4* dst = reinterpret_cast<float4*>(sm);
        for (int i = tid; i < WTOT / 4; i += BLK) dst[i] = src[i];
    }
    __syncthreads();

    float* sact  = sm + WTOT;
    float* scell = sm + WTOT + 48 * BLK;
    float* shid  = sm + WTOT + 48 * BLK + 32 * BLK;

    for (int b = blockIdx.x * BLK + tid; b < n; b += gridDim.x * BLK) {
        // zero state
#pragma unroll
        for (int k = 0; k < 30; ++k) {
            scell[k * BLK + tid] = 0.0f;
            shid[k * BLK + tid]  = 0.0f;
        }
        const float* xb = x + (size_t)b * 24;

#pragma unroll 1
        for (int t = 0; t < 3; ++t) {
            float a[48];
            float4 xv0 = *reinterpret_cast<const float4*>(xb + t * 8);
            float4 xv1 = *reinterpret_cast<const float4*>(xb + t * 8 + 4);
            a[0] = xv0.x; a[1] = xv0.y; a[2] = xv0.z; a[3] = xv0.w;
            a[4] = xv1.x; a[5] = xv1.y; a[6] = xv1.z; a[7] = xv1.w;
#pragma unroll
            for (int k = 0; k < 30; ++k) a[8 + k] = shid[k * BLK + tid];
            a[38] = 0.0f; a[39] = 0.0f;
#pragma unroll
            for (int k = 40; k < 48; ++k) a[k] = 0.0f;

            // hs = hidden_transform(cat(x_t, hidden))  [linear]
            dense<40, 30, false>(sm + OFF_HT, sm + OFF_BHT, a, sact, tid);

            // a = tanh(W0eff hs + b0)
            load_act<30, 32>(a, sact, tid);
            dense<32, 30, true>(sm + OFF_W0, sm + OFF_B0, a, sact, tid);

            // a = tanh(W1 a + b1)
            load_act<30, 32>(a, sact, tid);
            dense<32, 45, true>(sm + OFF_W1, sm + OFF_B1, a, sact, tid);

            // a = tanh(W2 a + b2)
            load_act<45, 48>(a, sact, tid);
            dense<48, 40, true>(sm + OFF_W2, sm + OFF_B2, a, sact, tid);

            // a = tanh(W3 a + b3)
            load_act<40, 40>(a, sact, tid);
            dense<40, 30, true>(sm + OFF_W3, sm + OFF_B3, a, sact, tid);

            // gates + cell/hidden update, streamed per j (no 120-wide buffer)
            load_act<30, 32>(a, sact, tid);
#pragma unroll 1
            for (int j = 0; j < 30; ++j) {
                const float4* wr = reinterpret_cast<const float4*>(sm + OFF_GW + j * 4 * 32);
                float gate[4];
#pragma unroll
                for (int g = 0; g < 4; ++g) {
                    float s0 = 0.f, s1 = 0.f, s2 = 0.f, s3 = 0.f;
#pragma unroll
                    for (int q = 0; q < 8; ++q) {
                        float4 wv = wr[g * 8 + q];
                        s0 = fmaf(wv.x, a[4 * q + 0], s0);
                        s1 = fmaf(wv.y, a[4 * q + 1], s1);
                        s2 = fmaf(wv.z, a[4 * q + 2], s2);
                        s3 = fmaf(wv.w, a[4 * q + 3], s3);
                    }
                    gate[g] = tanh_fast(((s0 + s1) + (s2 + s3)) + sm[OFF_BG + j * 4 + g]);
                }
                float ig = sigmoid_fast(gate[0]);
                float fg = sigmoid_fast(gate[1]);
                float og = sigmoid_fast(gate[2]);
                float gg = tanh_fast(gate[3]);
                float c  = fmaf(fg, scell[j * BLK + tid], ig * gg);
                scell[j * BLK + tid] = c;
                shid[j * BLK + tid]  = og * tanh_fast(c);
            }
        }

        // out = hidden . pw + pb   (folded predict heads)
        {
            float a[48];
            load_act<30, 32>(a, shid, tid);
            const float4* wr = reinterpret_cast<const float4*>(sm + OFF_PW);
            float s0 = 0.f, s1 = 0.f, s2 = 0.f, s3 = 0.f;
#pragma unroll
            for (int q = 0; q < 8; ++q) {
                float4 wv = wr[q];
                s0 = fmaf(wv.x, a[4 * q + 0], s0);
                s1 = fmaf(wv.y, a[4 * q + 1], s1);
                s2 = fmaf(wv.z, a[4 * q + 2], s2);
                s3 = fmaf(wv.w, a[4 * q + 3], s3);
            }
            out[b] = ((s0 + s1) + (s2 + s3)) + sm[OFF_PB];
        }
    }
}

// ---------------- launch ----------------
extern "C" void kernel_launch(void* const* d_in, const int* in_sizes, int n_in,
                              void* d_out, int out_size)
{
    const float* x    = (const float*)d_in[0];
    const float* ht_W = (const float*)d_in[1];
    const float* ht_b = (const float*)d_in[2];
    const float* m_W0 = (const float*)d_in[3];
    const float* m_b0 = (const float*)d_in[4];
    const float* m_W1 = (const float*)d_in[5];
    const float* m_b1 = (const float*)d_in[6];
    const float* m_W2 = (const float*)d_in[7];
    const float* m_b2 = (const float*)d_in[8];
    const float* m_W3 = (const float*)d_in[9];
    const float* m_b3 = (const float*)d_in[10];
    const float* gW   = (const float*)d_in[11];
    const float* gb   = (const float*)d_in[12];
    const float* p1W  = (const float*)d_in[13];
    const float* p1b  = (const float*)d_in[14];
    const float* p2W  = (const float*)d_in[15];
    const float* p2b  = (const float*)d_in[16];

    cudaFuncSetAttribute(lstm_main, cudaFuncAttributeMaxDynamicSharedMemorySize, SM_BYTES);

    prep_kernel<<<1, 256>>>(ht_W, ht_b, m_W0, m_b0, m_W1, m_b1, m_W2, m_b2,
                            m_W3, m_b3, gW, gb, p1W, p1b, p2W, p2b);

    lstm_main<<<296, BLK, SM_BYTES>>>(x, (float*)d_out, out_size);
}

// round 2
// speedup vs baseline: 1.0310x; 1.0310x over previous
#include <cuda_runtime.h>
#include <math.h>

#define BLK 224
typedef unsigned long long u64;

// ---------------- packed duplicated weight layout (floats; each logical weight
// stored twice: (w,w) forming an f32x2 pair). Row stride = KP*2 floats. ----------
constexpr int OFF_HT  = 0;        // 30 x 40 pairs
constexpr int OFF_BHT = 2400;     // 32 pairs
constexpr int OFF_W0  = 2464;     // 30 x 32 pairs (W0eff = W0[:, :30] + W0[:, 30:])
constexpr int OFF_B0  = 4384;     // 32 pairs
constexpr int OFF_W1  = 4448;     // 45 x 32 pairs
constexpr int OFF_B1  = 7328;     // 48 pairs
constexpr int OFF_W2  = 7424;     // 40 x 48 pairs
constexpr int OFF_B2  = 11264;    // 40 pairs
constexpr int OFF_W3  = 11344;    // 30 x 40 pairs
constexpr int OFF_B3  = 13744;    // 32 pairs
constexpr int OFF_GW  = 13808;    // 30 x 4 x 32 pairs (gate rows interleaved: i,f,o,g)
constexpr int OFF_BG  = 21488;    // 120 pairs
constexpr int OFF_PW  = 21728;    // 32 pairs (folded p2@p1)
constexpr int OFF_PB  = 21792;    // 1 pair
constexpr int WTOT2   = 21800;    // floats (pad to mult of 4)

__device__ float g_w[WTOT2];

// shared: [0,WTOT2) dup weights | cell pairs 30*BLK | act pairs 45*BLK
constexpr int SM_CELL   = WTOT2;                    // 30*BLK*2 floats
constexpr int SM_ACT    = WTOT2 + 30 * BLK * 2;     // 45*BLK*2 floats
constexpr int SM_FLOATS = SM_ACT + 45 * BLK * 2;
constexpr int SM_BYTES  = SM_FLOATS * 4;            // 221600 B

// ---------------- prep kernel: fold + pack + duplicate weights ----------------
__global__ void prep_kernel(
    const float* __restrict__ ht_W, const float* __restrict__ ht_b,
    const float* __restrict__ m_W0, const float* __restrict__ m_b0,
    const float* __restrict__ m_W1, const float* __restrict__ m_b1,
    const float* __restrict__ m_W2, const float* __restrict__ m_b2,
    const float* __restrict__ m_W3, const float* __restrict__ m_b3,
    const float* __restrict__ gW,   const float* __restrict__ gb,
    const float* __restrict__ p1W,  const float* __restrict__ p1b,
    const float* __restrict__ p2W,  const float* __restrict__ p2b)
{
    const int tid = threadIdx.x;
    const int NT  = blockDim.x;
    for (int i = tid; i < WTOT2; i += NT) g_w[i] = 0.0f;
    __syncthreads();

#define PUT(off, idx, v) do { float _v = (v); g_w[(off) + 2*(idx)] = _v; g_w[(off) + 2*(idx) + 1] = _v; } while (0)

    // ht_W (30 x 38) -> rows of 40
    for (int i = tid; i < 30 * 38; i += NT)
        PUT(OFF_HT, (i / 38) * 40 + (i % 38), ht_W[i]);
    for (int i = tid; i < 30; i += NT) PUT(OFF_BHT, i, ht_b[i]);

    // W0eff (30 x 30) -> rows of 32
    for (int i = tid; i < 30 * 30; i += NT) {
        int j = i / 30, k = i % 30;
        PUT(OFF_W0, j * 32 + k, m_W0[j * 60 + k] + m_W0[j * 60 + 30 + k]);
    }
    for (int i = tid; i < 30; i += NT) PUT(OFF_B0, i, m_b0[i]);

    // W1 (45 x 30) -> rows of 32
    for (int i = tid; i < 45 * 30; i += NT)
        PUT(OFF_W1, (i / 30) * 32 + (i % 30), m_W1[i]);
    for (int i = tid; i < 45; i += NT) PUT(OFF_B1, i, m_b1[i]);

    // W2 (40 x 45) -> rows of 48
    for (int i = tid; i < 40 * 45; i += NT)
        PUT(OFF_W2, (i / 45) * 48 + (i % 45), m_W2[i]);
    for (int i = tid; i < 40; i += NT) PUT(OFF_B2, i, m_b2[i]);

    // W3 (30 x 40) -> rows of 40
    for (int i = tid; i < 30 * 40; i += NT)
        PUT(OFF_W3, i, m_W3[i]);
    for (int i = tid; i < 30; i += NT) PUT(OFF_B3, i, m_b3[i]);

    // g_W (120 x 30): interleave 4 gate rows per j -> [j][g][32]
    for (int i = tid; i < 120 * 30; i += NT) {
        int r = i / 30, k = i % 30;
        int g = r / 30, jj = r % 30;
        PUT(OFF_GW, (jj * 4 + g) * 32 + k, gW[i]);
    }
    for (int i = tid; i < 120; i += NT) {
        int g = i / 30, jj = i % 30;
        PUT(OFF_BG, jj * 4 + g, gb[i]);
    }

    // fold predict heads
    for (int k = tid; k < 30; k += NT) {
        float s = 0.0f;
        for (int i = 0; i < 10; ++i) s += p2W[i] * p1W[i * 30 + k];
        PUT(OFF_PW, k, s);
    }
    if (tid == 0) {
        float s = p2b[0];
        for (int i = 0; i < 10; ++i) s += p2W[i] * p1b[i];
        PUT(OFF_PB, 0, s);
    }
#undef PUT
}

// ---------------- f32x2 packed helpers ----------------
__device__ __forceinline__ u64 fma2(u64 a, u64 b, u64 c) {
    u64 d; asm("fma.rn.f32x2 %0, %1, %2, %3;" : "=l"(d) : "l"(a), "l"(b), "l"(c)); return d;
}
__device__ __forceinline__ u64 add2(u64 a, u64 b) {
    u64 d; asm("add.rn.f32x2 %0, %1, %2;" : "=l"(d) : "l"(a), "l"(b)); return d;
}
__device__ __forceinline__ u64 pk(float lo, float hi) {
    u64 r; asm("mov.b64 %0, {%1, %2};" : "=l"(r) : "f"(lo), "f"(hi)); return r;
}
__device__ __forceinline__ void upk(u64 v, float& lo, float& hi) {
    asm("mov.b64 {%0, %1}, %2;" : "=f"(lo), "=f"(hi) : "l"(v));
}

// tanh(x) = 1 - 2/(1 + e^{2x}); overflow-safe, no abs/copysign, ~1e-6 rel err
__device__ __forceinline__ float tanh_e(float x) {
    float e; asm("ex2.approx.f32 %0, %1;" : "=f"(e) : "f"(x * 2.885390082f)); // 2*log2(e)
    float r; asm("rcp.approx.f32 %0, %1;" : "=f"(r) : "f"(e + 1.0f));
    return fmaf(-2.0f, r, 1.0f);
}
__device__ __forceinline__ float sig_e(float x) {
    float e; asm("ex2.approx.f32 %0, %1;" : "=f"(e) : "f"(x * -1.4426950408889634f));
    float r; asm("rcp.approx.f32 %0, %1;" : "=f"(r) : "f"(e + 1.0f));
    return r;
}
__device__ __forceinline__ u64 tanh2(u64 v) {
    float lo, hi; upk(v, lo, hi);
    return pk(tanh_e(lo), tanh_e(hi));
}

// ---------------- packed dense: A(reg pairs) @ W^T + b -> smem pair slots ----------------
template <int KP, int N, bool TANH>
__device__ __forceinline__ void dense2(const float* __restrict__ w,
                                       const float* __restrict__ bias,
                                       const u64 (&A)[48],
                                       float* __restrict__ outbuf, int tid)
{
#pragma unroll 1
    for (int j = 0; j < N; ++j) {
        const ulonglong2* wr = reinterpret_cast<const ulonglong2*>(w + j * KP * 2);
        u64 a0 = 0, a1 = 0, a2 = 0, a3 = 0;
#pragma unroll
        for (int q = 0; q < KP / 4; ++q) {
            ulonglong2 w0 = wr[2 * q];
            ulonglong2 w1 = wr[2 * q + 1];
            a0 = fma2(w0.x, A[4 * q + 0], a0);
            a1 = fma2(w0.y, A[4 * q + 1], a1);
            a2 = fma2(w1.x, A[4 * q + 2], a2);
            a3 = fma2(w1.y, A[4 * q + 3], a3);
        }
        u64 s = add2(add2(a0, a1), add2(a2, a3));
        s = add2(s, *reinterpret_cast<const u64*>(bias + 2 * j));
        if (TANH) s = tanh2(s);
        *reinterpret_cast<u64*>(outbuf + (size_t)(j * BLK + tid) * 2) = s;
    }
}

template <int K>
__device__ __forceinline__ void load_act(u64 (&A)[48], const float* __restrict__ buf, int tid)
{
#pragma unroll
    for (int k = 0; k < 48; ++k)
        A[k] = (k < K) ? *reinterpret_cast<const u64*>(buf + (size_t)(k * BLK + tid) * 2) : 0ULL;
}

// ---------------- main persistent kernel: 2 batch elements per thread ----------------
__global__ void __launch_bounds__(BLK, 1)
lstm_main(const float* __restrict__ x, float* __restrict__ out, int n)
{
    extern __shared__ float sm[];
    const int tid = threadIdx.x;

    // cooperative weight copy
    {
        const float4* src = reinterpret_cast<const float4*>(g_w);
        float4* dst = reinterpret_cast<float4*>(sm);
        for (int i = tid; i < WTOT2 / 4; i += BLK) dst[i] = src[i];
    }
    __syncthreads();

    float* scell = sm + SM_CELL;
    float* sact  = sm + SM_ACT;

    const int npairs = n >> 1;
    for (int p = blockIdx.x * BLK + tid; p < npairs; p += gridDim.x * BLK) {
        // zero cell state (pairs)
#pragma unroll
        for (int k = 0; k < 30; ++k)
            *reinterpret_cast<u64*>(scell + (size_t)(k * BLK + tid) * 2) = 0ULL;

        u64 h[30];
#pragma unroll
        for (int k = 0; k < 30; ++k) h[k] = 0ULL;

        const float* xb0 = x + (size_t)(2 * p) * 24;
        const float* xb1 = xb0 + 24;

#pragma unroll 1
        for (int t = 0; t < 3; ++t) {
            u64 A[48];
            float4 u0 = *reinterpret_cast<const float4*>(xb0 + t * 8);
            float4 u1 = *reinterpret_cast<const float4*>(xb0 + t * 8 + 4);
            float4 v0 = *reinterpret_cast<const float4*>(xb1 + t * 8);
            float4 v1 = *reinterpret_cast<const float4*>(xb1 + t * 8 + 4);
            A[0] = pk(u0.x, v0.x); A[1] = pk(u0.y, v0.y);
            A[2] = pk(u0.z, v0.z); A[3] = pk(u0.w, v0.w);
            A[4] = pk(u1.x, v1.x); A[5] = pk(u1.y, v1.y);
            A[6] = pk(u1.z, v1.z); A[7] = pk(u1.w, v1.w);
#pragma unroll
            for (int k = 0; k < 30; ++k) A[8 + k] = h[k];
#pragma unroll
            for (int k = 38; k < 48; ++k) A[k] = 0ULL;

            // hs = hidden_transform(cat(x_t, hidden))  [linear, no tanh]
            dense2<40, 30, false>(sm + OFF_HT, sm + OFF_BHT, A, sact, tid);

            load_act<30>(A, sact, tid);
            dense2<32, 30, true>(sm + OFF_W0, sm + OFF_B0, A, sact, tid);

            load_act<30>(A, sact, tid);
            dense2<32, 45, true>(sm + OFF_W1, sm + OFF_B1, A, sact, tid);

            load_act<45>(A, sact, tid);
            dense2<48, 40, true>(sm + OFF_W2, sm + OFF_B2, A, sact, tid);

            load_act<40>(A, sact, tid);
            dense2<40, 30, true>(sm + OFF_W3, sm + OFF_B3, A, sact, tid);

            // gates + state update
            load_act<30>(A, sact, tid);
#pragma unroll 1
            for (int j = 0; j < 30; ++j) {
                u64 gate[4];
#pragma unroll
                for (int g = 0; g < 4; ++g) {
                    const ulonglong2* wr = reinterpret_cast<const ulonglong2*>(
                        sm + OFF_GW + (size_t)(j * 4 + g) * 64);
                    u64 a0 = 0, a1 = 0, a2 = 0, a3 = 0;
#pragma unroll
                    for (int q = 0; q < 8; ++q) {
                        ulonglong2 w0 = wr[2 * q];
                        ulonglong2 w1 = wr[2 * q + 1];
                        a0 = fma2(w0.x, A[4 * q + 0], a0);
                        a1 = fma2(w0.y, A[4 * q + 1], a1);
                        a2 = fma2(w1.x, A[4 * q + 2], a2);
                        a3 = fma2(w1.y, A[4 * q + 3], a3);
                    }
                    u64 s = add2(add2(a0, a1), add2(a2, a3));
                    s = add2(s, *reinterpret_cast<const u64*>(sm + OFF_BG + (j * 4 + g) * 2));
                    gate[g] = tanh2(s);   // extra tanh before split (faithful)
                }
                float i0, i1, f0, f1, o0, o1, g0, g1;
                upk(gate[0], i0, i1); upk(gate[1], f0, f1);
                upk(gate[2], o0, o1); upk(gate[3], g0, g1);
                float c0, c1;
                upk(*reinterpret_cast<const u64*>(scell + (size_t)(j * BLK + tid) * 2), c0, c1);
                float ig0 = sig_e(i0), ig1 = sig_e(i1);
                float fg0 = sig_e(f0), fg1 = sig_e(f1);
                float og0 = sig_e(o0), og1 = sig_e(o1);
                float gg0 = tanh_e(g0), gg1 = tanh_e(g1);
                c0 = fmaf(fg0, c0, ig0 * gg0);
                c1 = fmaf(fg1, c1, ig1 * gg1);
                *reinterpret_cast<u64*>(scell + (size_t)(j * BLK + tid) * 2) = pk(c0, c1);
                h[j] = pk(og0 * tanh_e(c0), og1 * tanh_e(c1));
            }
        }

        // out = hidden . pw + pb (folded heads); packed dot over 32 pairs
        {
            u64 A[32];
#pragma unroll
            for (int k = 0; k < 30; ++k) A[k] = h[k];
            A[30] = 0ULL; A[31] = 0ULL;
            const ulonglong2* wr = reinterpret_cast<const ulonglong2*>(sm + OFF_PW);
            u64 a0 = 0, a1 = 0, a2 = 0, a3 = 0;
#pragma unroll
            for (int q = 0; q < 8; ++q) {
                ulonglong2 w0 = wr[2 * q];
                ulonglong2 w1 = wr[2 * q + 1];
                a0 = fma2(w0.x, A[4 * q + 0], a0);
                a1 = fma2(w0.y, A[4 * q + 1], a1);
                a2 = fma2(w1.x, A[4 * q + 2], a2);
                a3 = fma2(w1.y, A[4 * q + 3], a3);
            }
            u64 s = add2(add2(a0, a1), add2(a2, a3));
            s = add2(s, *reinterpret_cast<const u64*>(sm + OFF_PB));
            *reinterpret_cast<u64*>(out + (size_t)2 * p) = s;  // two outputs, one STG.64
        }
    }
}

// ---------------- launch ----------------
extern "C" void kernel_launch(void* const* d_in, const int* in_sizes, int n_in,
                              void* d_out, int out_size)
{
    const float* x    = (const float*)d_in[0];
    const float* ht_W = (const float*)d_in[1];
    const float* ht_b = (const float*)d_in[2];
    const float* m_W0 = (const float*)d_in[3];
    const float* m_b0 = (const float*)d_in[4];
    const float* m_W1 = (const float*)d_in[5];
    const float* m_b1 = (const float*)d_in[6];
    const float* m_W2 = (const float*)d_in[7];
    const float* m_b2 = (const float*)d_in[8];
    const float* m_W3 = (const float*)d_in[9];
    const float* m_b3 = (const float*)d_in[10];
    const float* gW   = (const float*)d_in[11];
    const float* gb   = (const float*)d_in[12];
    const float* p1W  = (const float*)d_in[13];
    const float* p1b  = (const float*)d_in[14];
    const float* p2W  = (const float*)d_in[15];
    const float* p2b  = (const float*)d_in[16];

    cudaFuncSetAttribute(lstm_main, cudaFuncAttributeMaxDynamicSharedMemorySize, SM_BYTES);

    prep_kernel<<<1, 256>>>(ht_W, ht_b, m_W0, m_b0, m_W1, m_b1, m_W2, m_b2,
                            m_W3, m_b3, gW, gb, p1W, p1b, p2W, p2b);

    lstm_main<<<148, BLK, SM_BYTES>>>(x, (float*)d_out, out_size);
}

// round 3
// speedup vs baseline: 1.0729x; 1.0407x over previous
#include <cuda_runtime.h>

#define BLK 224
#define GRID 296
typedef unsigned long long u64;

// ---------------- packed single-copy weight layout (floats) ----------------
// Rows K-padded to multiple of 8; pads are ZERO; all rows 16B-aligned.
constexpr int OFF_HT  = 0;       // 30 x 40  (in = [x(8), hidden(30), 0,0])
constexpr int OFF_W0  = 1200;    // 30 x 32  (W0eff = W0[:, :30] + W0[:, 30:])
constexpr int OFF_W1  = 2160;    // 45 x 32
constexpr int OFF_W2  = 3600;    // 40 x 48
constexpr int OFF_W3  = 5520;    // 30 x 40
constexpr int OFF_GW  = 6720;    // 30 x 4 x 32 (gate rows interleaved per j: i,f,o,g)
constexpr int OFF_PW  = 10560;   // 32 (folded p2@p1)
constexpr int OFF_BHT = 10592;   // 30
constexpr int OFF_B0  = 10624;   // 30
constexpr int OFF_B1  = 10656;   // 45
constexpr int OFF_B2  = 10704;   // 40
constexpr int OFF_B3  = 10744;   // 30
constexpr int OFF_BG  = 10776;   // 120
constexpr int OFF_PB  = 10896;   // 1
constexpr int WTOT    = 10900;   // mult of 4

__device__ float g_w[WTOT];

// shared: weights | act pairs (24 u64 slots/thread) | cell (30 f32/thread)
constexpr int SM_ACT    = WTOT;                 // 48*BLK floats
constexpr int SM_CELL   = WTOT + 48 * BLK;      // 30*BLK floats
constexpr int SM_FLOATS = SM_CELL + 30 * BLK;
constexpr int SM_BYTES  = SM_FLOATS * 4;        // 113,488 B -> 2 CTAs/SM

// ---------------- prep kernel ----------------
__global__ void prep_kernel(
    const float* __restrict__ ht_W, const float* __restrict__ ht_b,
    const float* __restrict__ m_W0, const float* __restrict__ m_b0,
    const float* __restrict__ m_W1, const float* __restrict__ m_b1,
    const float* __restrict__ m_W2, const float* __restrict__ m_b2,
    const float* __restrict__ m_W3, const float* __restrict__ m_b3,
    const float* __restrict__ gW,   const float* __restrict__ gb,
    const float* __restrict__ p1W,  const float* __restrict__ p1b,
    const float* __restrict__ p2W,  const float* __restrict__ p2b)
{
    const int tid = threadIdx.x;
    const int NT  = blockDim.x;
    for (int i = tid; i < WTOT; i += NT) g_w[i] = 0.0f;
    __syncthreads();

    for (int i = tid; i < 30 * 38; i += NT)
        g_w[OFF_HT + (i / 38) * 40 + (i % 38)] = ht_W[i];
    for (int i = tid; i < 30; i += NT) g_w[OFF_BHT + i] = ht_b[i];

    for (int i = tid; i < 30 * 30; i += NT) {
        int j = i / 30, k = i % 30;
        g_w[OFF_W0 + j * 32 + k] = m_W0[j * 60 + k] + m_W0[j * 60 + 30 + k];
    }
    for (int i = tid; i < 30; i += NT) g_w[OFF_B0 + i] = m_b0[i];

    for (int i = tid; i < 45 * 30; i += NT)
        g_w[OFF_W1 + (i / 30) * 32 + (i % 30)] = m_W1[i];
    for (int i = tid; i < 45; i += NT) g_w[OFF_B1 + i] = m_b1[i];

    for (int i = tid; i < 40 * 45; i += NT)
        g_w[OFF_W2 + (i / 45) * 48 + (i % 45)] = m_W2[i];
    for (int i = tid; i < 40; i += NT) g_w[OFF_B2 + i] = m_b2[i];

    for (int i = tid; i < 30 * 40; i += NT)
        g_w[OFF_W3 + i] = m_W3[i];
    for (int i = tid; i < 30; i += NT) g_w[OFF_B3 + i] = m_b3[i];

    for (int i = tid; i < 120 * 30; i += NT) {
        int r = i / 30, k = i % 30;
        int g = r / 30, jj = r % 30;
        g_w[OFF_GW + (jj * 4 + g) * 32 + k] = gW[i];
    }
    for (int i = tid; i < 120; i += NT) {
        int g = i / 30, jj = i % 30;
        g_w[OFF_BG + jj * 4 + g] = gb[i];
    }

    for (int k = tid; k < 30; k += NT) {
        float s = 0.0f;
        for (int i = 0; i < 10; ++i) s += p2W[i] * p1W[i * 30 + k];
        g_w[OFF_PW + k] = s;
    }
    if (tid == 0) {
        float s = p2b[0];
        for (int i = 0; i < 10; ++i) s += p2W[i] * p1b[i];
        g_w[OFF_PB] = s;
    }
}

// ---------------- f32x2 helpers ----------------
__device__ __forceinline__ u64 fma2(u64 a, u64 b, u64 c) {
    u64 d; asm("fma.rn.f32x2 %0, %1, %2, %3;" : "=l"(d) : "l"(a), "l"(b), "l"(c)); return d;
}
__device__ __forceinline__ u64 add2(u64 a, u64 b) {
    u64 d; asm("add.rn.f32x2 %0, %1, %2;" : "=l"(d) : "l"(a), "l"(b)); return d;
}
__device__ __forceinline__ void upk(u64 v, float& lo, float& hi) {
    asm("mov.b64 {%0, %1}, %2;" : "=f"(lo), "=f"(hi) : "l"(v));
}

// tanh(x) = 1 - 2/(1 + e^{2x}); overflow-safe, ~1e-6 rel err
__device__ __forceinline__ float tanh_e(float x) {
    float e; asm("ex2.approx.f32 %0, %1;" : "=f"(e) : "f"(x * 2.885390082f));
    float r; asm("rcp.approx.f32 %0, %1;" : "=f"(r) : "f"(e + 1.0f));
    return fmaf(-2.0f, r, 1.0f);
}
__device__ __forceinline__ float sig_e(float x) {
    float e; asm("ex2.approx.f32 %0, %1;" : "=f"(e) : "f"(x * -1.4426950408889634f));
    float r; asm("rcp.approx.f32 %0, %1;" : "=f"(r) : "f"(e + 1.0f));
    return r;
}

// ---------------- K-packed dense: one element/thread ----------------
// acc2 accumulates (even-k, odd-k) partial sums; horizontal add at the end.
template <int KP, int N, bool TANH>
__device__ __forceinline__ void dense_kp(const float* __restrict__ w,
                                         const float* __restrict__ bias,
                                         const u64 (&A)[24],
                                         float* __restrict__ act, int tid)
{
#pragma unroll 1
    for (int j = 0; j < N; ++j) {
        const ulonglong2* wr = reinterpret_cast<const ulonglong2*>(w + j * KP);
        u64 a0 = 0, a1 = 0, a2 = 0, a3 = 0;
#pragma unroll
        for (int q = 0; q < KP / 8; ++q) {
            ulonglong2 w0 = wr[2 * q];
            ulonglong2 w1 = wr[2 * q + 1];
            a0 = fma2(w0.x, A[4 * q + 0], a0);
            a1 = fma2(w0.y, A[4 * q + 1], a1);
            a2 = fma2(w1.x, A[4 * q + 2], a2);
            a3 = fma2(w1.y, A[4 * q + 3], a3);
        }
        float lo, hi;
        upk(add2(add2(a0, a1), add2(a2, a3)), lo, hi);
        float r = (lo + hi) + bias[j];
        if (TANH) r = tanh_e(r);
        act[(size_t)(((unsigned)j >> 1) * BLK + tid) * 2 + (j & 1)] = r;
    }
}

template <int NP>
__device__ __forceinline__ void loadA(u64 (&A)[24], const float* __restrict__ act, int tid)
{
#pragma unroll
    for (int p = 0; p < NP; ++p)
        A[p] = *reinterpret_cast<const u64*>(act + (size_t)(p * BLK + tid) * 2);
}

// ---------------- main persistent kernel ----------------
__global__ void __launch_bounds__(BLK, 2)
lstm_main(const float* __restrict__ x, float* __restrict__ out, int n)
{
    extern __shared__ float sm[];
    const int tid = threadIdx.x;

    {
        const float4* src = reinterpret_cast<const float4*>(g_w);
        float4* dst = reinterpret_cast<float4*>(sm);
        for (int i = tid; i < WTOT / 4; i += BLK) dst[i] = src[i];
    }
    float* sact  = sm + SM_ACT;
    float* scell = sm + SM_CELL;
    // zero this thread's act slots once (pads must be finite forever)
#pragma unroll
    for (int p = 0; p < 24; ++p)
        *reinterpret_cast<u64*>(sact + (size_t)(p * BLK + tid) * 2) = 0ULL;
    __syncthreads();

    for (int b = blockIdx.x * BLK + tid; b < n; b += GRID * BLK) {
#pragma unroll
        for (int j = 0; j < 30; ++j) scell[j * BLK + tid] = 0.0f;

        const u64* xb = reinterpret_cast<const u64*>(x + (size_t)b * 24);

#pragma unroll 1
        for (int t = 0; t < 3; ++t) {
            u64 A[24];
            A[0] = xb[t * 4 + 0]; A[1] = xb[t * 4 + 1];
            A[2] = xb[t * 4 + 2]; A[3] = xb[t * 4 + 3];
            if (t == 0) {
#pragma unroll
                for (int p = 0; p < 15; ++p) A[4 + p] = 0ULL;
            } else {
#pragma unroll
                for (int p = 0; p < 15; ++p)
                    A[4 + p] = *reinterpret_cast<const u64*>(sact + (size_t)(p * BLK + tid) * 2);
            }
            A[19] = 0ULL;

            // hs = hidden_transform(cat(x_t, hidden))  [linear]
            dense_kp<40, 30, false>(sm + OFF_HT, sm + OFF_BHT, A, sact, tid);

            loadA<16>(A, sact, tid);
            dense_kp<32, 30, true>(sm + OFF_W0, sm + OFF_B0, A, sact, tid);

            loadA<16>(A, sact, tid);
            dense_kp<32, 45, true>(sm + OFF_W1, sm + OFF_B1, A, sact, tid);

            loadA<24>(A, sact, tid);   // 45 real + zero pads (idx 45..47 zeroed)
            dense_kp<48, 40, true>(sm + OFF_W2, sm + OFF_B2, A, sact, tid);

            loadA<20>(A, sact, tid);
            dense_kp<40, 30, true>(sm + OFF_W3, sm + OFF_B3, A, sact, tid);

            // gates + state update (reads A from regs; rewrites act slots with h)
            loadA<16>(A, sact, tid);
#pragma unroll 1
            for (int j = 0; j < 30; ++j) {
                float gate[4];
#pragma unroll
                for (int g = 0; g < 4; ++g) {
                    const ulonglong2* wr = reinterpret_cast<const ulonglong2*>(
                        sm + OFF_GW + (size_t)(j * 4 + g) * 32);
                    u64 a0 = 0, a1 = 0, a2 = 0, a3 = 0;
#pragma unroll
                    for (int q = 0; q < 4; ++q) {
                        ulonglong2 w0 = wr[2 * q];
                        ulonglong2 w1 = wr[2 * q + 1];
                        a0 = fma2(w0.x, A[4 * q + 0], a0);
                        a1 = fma2(w0.y, A[4 * q + 1], a1);
                        a2 = fma2(w1.x, A[4 * q + 2], a2);
                        a3 = fma2(w1.y, A[4 * q + 3], a3);
                    }
                    float lo, hi;
                    upk(add2(add2(a0, a1), add2(a2, a3)), lo, hi);
                    gate[g] = tanh_e((lo + hi) + sm[OFF_BG + j * 4 + g]);
                }
                float ig = sig_e(gate[0]);
                float fg = sig_e(gate[1]);
                float og = sig_e(gate[2]);
                float gg = tanh_e(gate[3]);
                float c  = fmaf(fg, scell[j * BLK + tid], ig * gg);
                scell[j * BLK + tid] = c;
                sact[(size_t)(((unsigned)j >> 1) * BLK + tid) * 2 + (j & 1)] = og * tanh_e(c);
            }
        }

        // out = hidden . pw + pb (folded heads)
        {
            u64 A[24];
            loadA<16>(A, sact, tid);
            const ulonglong2* wr = reinterpret_cast<const ulonglong2*>(sm + OFF_PW);
            u64 a0 = 0, a1 = 0, a2 = 0, a3 = 0;
#pragma unroll
            for (int q = 0; q < 4; ++q) {
                ulonglong2 w0 = wr[2 * q];
                ulonglong2 w1 = wr[2 * q + 1];
                a0 = fma2(w0.x, A[4 * q + 0], a0);
                a1 = fma2(w0.y, A[4 * q + 1], a1);
                a2 = fma2(w1.x, A[4 * q + 2], a2);
                a3 = fma2(w1.y, A[4 * q + 3], a3);
            }
            float lo, hi;
            upk(add2(add2(a0, a1), add2(a2, a3)), lo, hi);
            out[b] = (lo + hi) + sm[OFF_PB];
        }
    }
}

// ---------------- launch ----------------
extern "C" void kernel_launch(void* const* d_in, const int* in_sizes, int n_in,
                              void* d_out, int out_size)
{
    const float* x    = (const float*)d_in[0];
    const float* ht_W = (const float*)d_in[1];
    const float* ht_b = (const float*)d_in[2];
    const float* m_W0 = (const float*)d_in[3];
    const float* m_b0 = (const float*)d_in[4];
    const float* m_W1 = (const float*)d_in[5];
    const float* m_b1 = (const float*)d_in[6];
    const float* m_W2 = (const float*)d_in[7];
    const float* m_b2 = (const float*)d_in[8];
    const float* m_W3 = (const float*)d_in[9];
    const float* m_b3 = (const float*)d_in[10];
    const float* gW   = (const float*)d_in[11];
    const float* gb   = (const float*)d_in[12];
    const float* p1W  = (const float*)d_in[13];
    const float* p1b  = (const float*)d_in[14];
    const float* p2W  = (const float*)d_in[15];
    const float* p2b  = (const float*)d_in[16];

    cudaFuncSetAttribute(lstm_main, cudaFuncAttributeMaxDynamicSharedMemorySize, SM_BYTES);

    prep_kernel<<<1, 256>>>(ht_W, ht_b, m_W0, m_b0, m_W1, m_b1, m_W2, m_b2,
                            m_W3, m_b3, gW, gb, p1W, p1b, p2W, p2b);

    lstm_main<<<GRID, BLK, SM_BYTES>>>(x, (float*)d_out, out_size);
}

// round 5
// speedup vs baseline: 2.2132x; 2.0628x over previous
#include <cuda_runtime.h>
#include <cuda_bf16.h>
#include <stdint.h>

#define BLK 128
#define GRID 296

// ---------------- fragment image offsets (uint32 units) ----------------
// Per layer, per split(hi/lo): [NT][KT][lane(32)][2 regs]
constexpr int HT_H = 0,    HT_L = 768;    // NT4 KT3
constexpr int L0_H = 1536, L0_L = 2048;   // NT4 KT2
constexpr int L1_H = 2560, L1_L = 3328;   // NT6 KT2
constexpr int L2_H = 4096, L2_L = 5056;   // NT5 KT3
constexpr int L3_H = 6016, L3_L = 6784;   // NT4 KT3
constexpr int GW_H = 7552, GW_L = 9600;   // NT16 KT2
// biases (float units, same 4B array)
constexpr int B_HT = 11648, B_L0 = 11680, B_L1 = 11712, B_L2 = 11760, B_L3 = 11800, B_GW = 11832;
constexpr int HEADW = 11960;   // pw[30], pb at 11990
constexpr int SWTOT = 11992;   // 47,968 bytes

__device__ uint32_t g_wf[SWTOT];

__device__ __forceinline__ uint32_t pack_bf16(float lo, float hi) {
    uint32_t r; asm("cvt.rn.bf16x2.f32 %0, %1, %2;" : "=r"(r) : "f"(hi), "f"(lo)); return r;
}

// ---------------- prep kernel: weights -> exact B-fragment layout, hi/lo split ----------------
__global__ void prep_kernel(
    const float* __restrict__ ht_W, const float* __restrict__ ht_b,
    const float* __restrict__ m_W0, const float* __restrict__ m_b0,
    const float* __restrict__ m_W1, const float* __restrict__ m_b1,
    const float* __restrict__ m_W2, const float* __restrict__ m_b2,
    const float* __restrict__ m_W3, const float* __restrict__ m_b3,
    const float* __restrict__ gW,   const float* __restrict__ gb,
    const float* __restrict__ p1W,  const float* __restrict__ p1b,
    const float* __restrict__ p2W,  const float* __restrict__ p2b)
{
    const int tid = threadIdx.x;
    const int NTH = blockDim.x;

    auto fill = [&](int baseH, int baseL, int NT, int KT, auto getw) {
        for (int i = tid; i < NT * KT * 64; i += NTH) {
            int reg = i & 1, ln = (i >> 1) & 31, tk = i >> 6;
            int kt = tk % KT, nt = tk / KT;
            int nn = nt * 8 + (ln >> 2);
            int k0 = kt * 16 + (ln & 3) * 2 + reg * 8;
            float w0 = getw(nn, k0), w1 = getw(nn, k0 + 1);
            uint32_t hi = pack_bf16(w0, w1);
            float r0 = w0 - __uint_as_float(hi << 16);
            float r1 = w1 - __uint_as_float(hi & 0xFFFF0000u);
            g_wf[baseH + i] = hi;
            g_wf[baseL + i] = pack_bf16(r0, r1);
        }
    };

    fill(HT_H, HT_L, 4, 3, [&](int n, int k) {
        return (n < 30 && k < 38) ? ht_W[n * 38 + k] : 0.0f; });
    fill(L0_H, L0_L, 4, 2, [&](int n, int k) {
        return (n < 30 && k < 30) ? (m_W0[n * 60 + k] + m_W0[n * 60 + 30 + k]) : 0.0f; });
    fill(L1_H, L1_L, 6, 2, [&](int n, int k) {
        return (n < 45 && k < 30) ? m_W1[n * 30 + k] : 0.0f; });
    fill(L2_H, L2_L, 5, 3, [&](int n, int k) {
        return (n < 40 && k < 45) ? m_W2[n * 45 + k] : 0.0f; });
    fill(L3_H, L3_L, 4, 3, [&](int n, int k) {
        return (n < 30 && k < 40) ? m_W3[n * 40 + k] : 0.0f; });
    fill(GW_H, GW_L, 16, 2, [&](int n, int k) {
        int g = n >> 5, jj = n & 31;
        return (jj < 30 && k < 30) ? gW[(g * 30 + jj) * 30 + k] : 0.0f; });

    float* gf = reinterpret_cast<float*>(g_wf);
    for (int i = tid; i < 32; i += NTH)  gf[B_HT + i] = (i < 30) ? ht_b[i] : 0.0f;
    for (int i = tid; i < 32; i += NTH)  gf[B_L0 + i] = (i < 30) ? m_b0[i] : 0.0f;
    for (int i = tid; i < 48; i += NTH)  gf[B_L1 + i] = (i < 45) ? m_b1[i] : 0.0f;
    for (int i = tid; i < 40; i += NTH)  gf[B_L2 + i] = m_b2[i];
    for (int i = tid; i < 32; i += NTH)  gf[B_L3 + i] = (i < 30) ? m_b3[i] : 0.0f;
    for (int i = tid; i < 128; i += NTH) {
        int g = i >> 5, jj = i & 31;
        gf[B_GW + i] = (jj < 30) ? gb[g * 30 + jj] : 0.0f;
    }
    for (int k = tid; k < 30; k += NTH) {
        float s = 0.0f;
        for (int i = 0; i < 10; ++i) s += p2W[i] * p1W[i * 30 + k];
        gf[HEADW + k] = s;
    }
    if (tid == 0) {
        float s = p2b[0];
        for (int i = 0; i < 10; ++i) s += p2W[i] * p1b[i];
        gf[HEADW + 30] = s;
    }
}

// ---------------- math ----------------
__device__ __forceinline__ float tanh_e(float x) {
    float e; asm("ex2.approx.f32 %0, %1;" : "=f"(e) : "f"(x * 2.885390082f));
    float r; asm("rcp.approx.f32 %0, %1;" : "=f"(r) : "f"(e + 1.0f));
    return fmaf(-2.0f, r, 1.0f);
}
__device__ __forceinline__ float sig_e(float x) {
    float e; asm("ex2.approx.f32 %0, %1;" : "=f"(e) : "f"(x * -1.4426950408889634f));
    float r; asm("rcp.approx.f32 %0, %1;" : "=f"(r) : "f"(e + 1.0f));
    return r;
}

// ---------------- HMMA m16n8k16 bf16 ----------------
__device__ __forceinline__ void mma_bf16(float d[4], const uint32_t a[4],
                                         uint32_t b0, uint32_t b1) {
    asm volatile("mma.sync.aligned.m16n8k16.row.col.f32.bf16.bf16.f32 "
        "{%0,%1,%2,%3}, {%4,%5,%6,%7}, {%8,%9}, {%0,%1,%2,%3};"
        : "+f"(d[0]), "+f"(d[1]), "+f"(d[2]), "+f"(d[3])
        : "r"(a[0]), "r"(a[1]), "r"(a[2]), "r"(a[3]), "r"(b0), "r"(b1));
}

// D tile for one nt, both m-tiles, bias-initialized, 3-term hi/lo split
template <int KT>
__device__ __forceinline__ void dense_nt(
    const uint32_t (&aH)[2][3][4], const uint32_t (&aL)[2][3][4],
    const uint32_t* __restrict__ wfH, const uint32_t* __restrict__ wfL,
    const float* __restrict__ bias, int nt, int lane, int tq,
    float d0[4], float d1[4])
{
    float2 bb = *reinterpret_cast<const float2*>(bias + nt * 8 + tq * 2);
    d0[0] = bb.x; d0[1] = bb.y; d0[2] = bb.x; d0[3] = bb.y;
    d1[0] = bb.x; d1[1] = bb.y; d1[2] = bb.x; d1[3] = bb.y;
#pragma unroll
    for (int kt = 0; kt < KT; ++kt) {
        uint2 bh = *reinterpret_cast<const uint2*>(wfH + ((nt * KT + kt) * 32 + lane) * 2);
        mma_bf16(d0, aH[0][kt], bh.x, bh.y);
        mma_bf16(d1, aH[1][kt], bh.x, bh.y);
        mma_bf16(d0, aL[0][kt], bh.x, bh.y);
        mma_bf16(d1, aL[1][kt], bh.x, bh.y);
        uint2 bl = *reinterpret_cast<const uint2*>(wfL + ((nt * KT + kt) * 32 + lane) * 2);
        mma_bf16(d0, aH[0][kt], bl.x, bl.y);
        mma_bf16(d1, aH[1][kt], bl.x, bl.y);
    }
}

// value pair -> (hi bf16x2, lo bf16x2), optional tanh
template <bool TANH>
__device__ __forceinline__ void pack_pair(float v0, float v1, uint32_t& h, uint32_t& l) {
    if (TANH) { v0 = tanh_e(v0); v1 = tanh_e(v1); }
    h = pack_bf16(v0, v1);
    float f0 = __uint_as_float(h << 16);
    float f1 = __uint_as_float(h & 0xFFFF0000u);
    l = pack_bf16(v0 - f0, v1 - f1);
}

// two D tiles (even nt, odd nt) -> one A k-tile fragment
template <bool TANH>
__device__ __forceinline__ void conv_tile(const float de[4], const float dd[4],
                                          uint32_t aH[4], uint32_t aL[4]) {
    pack_pair<TANH>(de[0], de[1], aH[0], aL[0]);
    pack_pair<TANH>(de[2], de[3], aH[1], aL[1]);
    pack_pair<TANH>(dd[0], dd[1], aH[2], aL[2]);
    pack_pair<TANH>(dd[2], dd[3], aH[3], aL[3]);
}

template <int KT_IN, int NT, int KT_OUT, bool TANH>
__device__ __forceinline__ void run_layer(
    const uint32_t (&inH)[2][3][4], const uint32_t (&inL)[2][3][4],
    uint32_t (&outH)[2][3][4], uint32_t (&outL)[2][3][4],
    const uint32_t* __restrict__ wfH, const uint32_t* __restrict__ wfL,
    const float* __restrict__ bias, int lane, int tq)
{
#pragma unroll
    for (int ko = 0; ko < KT_OUT; ++ko) {
        float de0[4], de1[4], dd0[4], dd1[4];
        dense_nt<KT_IN>(inH, inL, wfH, wfL, bias, 2 * ko, lane, tq, de0, de1);
        if (2 * ko + 1 < NT) {
            dense_nt<KT_IN>(inH, inL, wfH, wfL, bias, 2 * ko + 1, lane, tq, dd0, dd1);
        } else {
#pragma unroll
            for (int q = 0; q < 4; ++q) { dd0[q] = 0.0f; dd1[q] = 0.0f; }
        }
        conv_tile<TANH>(de0, dd0, outH[0][ko], outL[0][ko]);
        conv_tile<TANH>(de1, dd1, outH[1][ko], outL[1][ko]);
    }
}

// ---------------- main kernel: 32 rows per warp, fully independent warps ----------------
__global__ void __launch_bounds__(BLK)
lstm_main(const float* __restrict__ x, float* __restrict__ out, int n)
{
    __shared__ uint32_t swf[SWTOT];
    const int tid = threadIdx.x;
    {
        const uint4* src = reinterpret_cast<const uint4*>(g_wf);
        uint4* dst = reinterpret_cast<uint4*>(swf);
        for (int i = tid; i < SWTOT / 4; i += BLK) dst[i] = src[i];
    }
    __syncthreads();

    const float* sb = reinterpret_cast<const float*>(swf);
    const int lane = tid & 31, warp = tid >> 5;
    const int quad = lane >> 2, tq = lane & 3;

    uint32_t XH[2][3][4], XL[2][3][4], YH[2][3][4], YL[2][3][4];
    float c[2][4][4];      // [mt][nt0][q]
    float p[2][2];         // head partials [mt][rh]

    const int ntiles = n >> 5;
    for (int tile = blockIdx.x * 4 + warp; tile < ntiles; tile += gridDim.x * 4) {
        const int rbase = tile << 5;
#pragma unroll
        for (int mt = 0; mt < 2; ++mt)
#pragma unroll
            for (int kt = 0; kt < 3; ++kt)
#pragma unroll
                for (int r = 0; r < 4; ++r) { XH[mt][kt][r] = 0u; XL[mt][kt][r] = 0u; }
#pragma unroll
        for (int mt = 0; mt < 2; ++mt)
#pragma unroll
            for (int a = 0; a < 4; ++a)
#pragma unroll
                for (int q = 0; q < 4; ++q) c[mt][a][q] = 0.0f;

#pragma unroll 1
        for (int t = 0; t < 3; ++t) {
            // x into X kt0 regs0,1 (k = tq*2, rows quad + 8*rh + 16*mt)
#pragma unroll
            for (int mt = 0; mt < 2; ++mt)
#pragma unroll
                for (int rh = 0; rh < 2; ++rh) {
                    int row = rbase + mt * 16 + rh * 8 + quad;
                    float2 xv = *reinterpret_cast<const float2*>(x + (size_t)row * 24 + t * 8 + tq * 2);
                    pack_pair<false>(xv.x, xv.y, XH[mt][0][rh], XL[mt][0][rh]);
                }

            run_layer<3, 4, 2, false>(XH, XL, YH, YL, swf + HT_H, swf + HT_L, sb + B_HT, lane, tq);
            run_layer<2, 4, 2, true >(YH, YL, XH, XL, swf + L0_H, swf + L0_L, sb + B_L0, lane, tq);
            run_layer<2, 6, 3, true >(XH, XL, YH, YL, swf + L1_H, swf + L1_L, sb + B_L1, lane, tq);
            run_layer<3, 5, 3, true >(YH, YL, XH, XL, swf + L2_H, swf + L2_L, sb + B_L2, lane, tq);
            run_layer<3, 4, 2, true >(XH, XL, YH, YL, swf + L3_H, swf + L3_L, sb + B_L3, lane, tq);

            // GW + gates: input Y (KT2); i/f/o/g at nt0, nt0+4, nt0+8, nt0+12
            p[0][0] = 0.0f; p[0][1] = 0.0f; p[1][0] = 0.0f; p[1][1] = 0.0f;
#pragma unroll
            for (int nt0 = 0; nt0 < 4; ++nt0) {
                float di0[4], di1[4], df0[4], df1[4], dq0[4], dq1[4], dg0[4], dg1[4];
                dense_nt<2>(YH, YL, swf + GW_H, swf + GW_L, sb + B_GW, nt0,      lane, tq, di0, di1);
                dense_nt<2>(YH, YL, swf + GW_H, swf + GW_L, sb + B_GW, nt0 + 4,  lane, tq, df0, df1);
                dense_nt<2>(YH, YL, swf + GW_H, swf + GW_L, sb + B_GW, nt0 + 8,  lane, tq, dq0, dq1);
                dense_nt<2>(YH, YL, swf + GW_H, swf + GW_L, sb + B_GW, nt0 + 12, lane, tq, dg0, dg1);
                float2 pw = *reinterpret_cast<const float2*>(sb + HEADW + nt0 * 8 + tq * 2);
                const int kt = (nt0 + 1) >> 1, ar = (nt0 + 1) & 1;
#pragma unroll
                for (int mt = 0; mt < 2; ++mt) {
                    const float* di = mt ? di1 : di0;
                    const float* df = mt ? df1 : df0;
                    const float* dq = mt ? dq1 : dq0;
                    const float* dg = mt ? dg1 : dg0;
                    float hh[4];
#pragma unroll
                    for (int q = 0; q < 4; ++q) {
                        float ig = sig_e(tanh_e(di[q]));
                        float fg = sig_e(tanh_e(df[q]));
                        float og = sig_e(tanh_e(dq[q]));
                        float gg = tanh_e(tanh_e(dg[q]));
                        float cc = fmaf(fg, c[mt][nt0][q], ig * gg);
                        c[mt][nt0][q] = cc;
                        hh[q] = og * tanh_e(cc);
                    }
                    p[mt][0] = fmaf(hh[0], pw.x, fmaf(hh[1], pw.y, p[mt][0]));
                    p[mt][1] = fmaf(hh[2], pw.x, fmaf(hh[3], pw.y, p[mt][1]));
                    pack_pair<false>(hh[0], hh[1], XH[mt][kt][ar * 2 + 0], XL[mt][kt][ar * 2 + 0]);
                    pack_pair<false>(hh[2], hh[3], XH[mt][kt][ar * 2 + 1], XL[mt][kt][ar * 2 + 1]);
                }
            }
        }

        // head: reduce over tq lanes (j-parallel), write rows
        float pb = sb[HEADW + 30];
#pragma unroll
        for (int mt = 0; mt < 2; ++mt)
#pragma unroll
            for (int rh = 0; rh < 2; ++rh) {
                float s = p[mt][rh];
                s += __shfl_xor_sync(0xffffffffu, s, 1);
                s += __shfl_xor_sync(0xffffffffu, s, 2);
                if (tq == 0)
                    out[rbase + mt * 16 + rh * 8 + quad] = s + pb;
            }
    }
}

// ---------------- launch ----------------
extern "C" void kernel_launch(void* const* d_in, const int* in_sizes, int n_in,
                              void* d_out, int out_size)
{
    const float* x    = (const float*)d_in[0];
    const float* ht_W = (const float*)d_in[1];
    const float* ht_b = (const float*)d_in[2];
    const float* m_W0 = (const float*)d_in[3];
    const float* m_b0 = (const float*)d_in[4];
    const float* m_W1 = (const float*)d_in[5];
    const float* m_b1 = (const float*)d_in[6];
    const float* m_W2 = (const float*)d_in[7];
    const float* m_b2 = (const float*)d_in[8];
    const float* m_W3 = (const float*)d_in[9];
    const float* m_b3 = (const float*)d_in[10];
    const float* gW   = (const float*)d_in[11];
    const float* gb   = (const float*)d_in[12];
    const float* p1W  = (const float*)d_in[13];
    const float* p1b  = (const float*)d_in[14];
    const float* p2W  = (const float*)d_in[15];
    const float* p2b  = (const float*)d_in[16];

    prep_kernel<<<1, 256>>>(ht_W, ht_b, m_W0, m_b0, m_W1, m_b1, m_W2, m_b2,
                            m_W3, m_b3, gW, gb, p1W, p1b, p2W, p2b);

    lstm_main<<<GRID, BLK>>>(x, (float*)d_out, out_size);
}